// round 7
// baseline (speedup 1.0000x reference)
#include <cuda_runtime.h>
#include <cuda_bf16.h>
#include <cuda_fp16.h>
#include <math.h>

#define S_LEN 1024
#define D_DIM 4096
#define NH 32
#define NKV 8
#define HD 128
#define FETCH_MAX 204

#define BM 128
#define BN 128
#define BK 32
#define LDS 40   // padded element stride (80B, 16B-aligned)

// -------- scratch (device globals: allocation-free) --------
__device__ float g_Q[(size_t)S_LEN * D_DIM];
__device__ float g_K[(size_t)S_LEN * NKV * HD];
__device__ float g_V[(size_t)S_LEN * NKV * HD];
__device__ float g_VT[(size_t)NKV * HD * S_LEN];
__device__ float g_P[(size_t)NH * S_LEN * S_LEN];
__device__ float g_AO[(size_t)S_LEN * D_DIM];
__device__ int   g_fetch[S_LEN];

// lower-triangle 128x128 block map for causal scores (8x8 grid -> 36 blocks)
__constant__ int c_IM36[36] = {0,1,1,2,2,2,3,3,3,3,4,4,4,4,4,5,5,5,5,5,5,
                               6,6,6,6,6,6,6,7,7,7,7,7,7,7,7};
__constant__ int c_JN36[36] = {0,0,1,0,1,2,0,1,2,3,0,1,2,3,4,0,1,2,3,4,5,
                               0,1,2,3,4,5,6,0,1,2,3,4,5,6,7};

// ---------------- tensor-core primitives ----------------
__device__ __forceinline__ void ldsm_x4(unsigned r[4], const void* p) {
    unsigned a = (unsigned)__cvta_generic_to_shared(p);
    asm volatile("ldmatrix.sync.aligned.m8n8.x4.shared.b16 {%0,%1,%2,%3}, [%4];"
                 : "=r"(r[0]), "=r"(r[1]), "=r"(r[2]), "=r"(r[3]) : "r"(a));
}
__device__ __forceinline__ void mma16816(float* d, const unsigned* a, const unsigned* b) {
    asm volatile("mma.sync.aligned.m16n8k16.row.col.f32.bf16.bf16.f32 "
                 "{%0,%1,%2,%3}, {%4,%5,%6,%7}, {%8,%9}, {%0,%1,%2,%3};"
                 : "+f"(d[0]), "+f"(d[1]), "+f"(d[2]), "+f"(d[3])
                 : "r"(a[0]), "r"(a[1]), "r"(a[2]), "r"(a[3]), "r"(b[0]), "r"(b[1]));
}
__device__ __forceinline__ void mma16816h(float* d, const unsigned* a, const unsigned* b) {
    asm volatile("mma.sync.aligned.m16n8k16.row.col.f32.f16.f16.f32 "
                 "{%0,%1,%2,%3}, {%4,%5,%6,%7}, {%8,%9}, {%0,%1,%2,%3};"
                 : "+f"(d[0]), "+f"(d[1]), "+f"(d[2]), "+f"(d[3])
                 : "r"(a[0]), "r"(a[1]), "r"(a[2]), "r"(a[3]), "r"(b[0]), "r"(b[1]));
}

// ============ split-bf16 GEMM (3-pass) with REGISTER DOUBLE-BUFFERED loads ============
template <int CAUSAL>
__global__ void __launch_bounds__(256, 2) bgemm_abT(
    const float* __restrict__ A, int lda, long long sA,
    const float* __restrict__ B, int ldb, long long sB, int zdivB,
    float* __restrict__ C, int ldc, long long sC,
    int K, float alpha, int clampK)
{
    A += (long long)blockIdx.z * sA;
    B += (long long)(blockIdx.z / zdivB) * sB;
    C += (long long)blockIdx.z * sC;
    __shared__ __align__(16) __nv_bfloat16 Ah[BM * LDS], Al[BM * LDS];
    __shared__ __align__(16) __nv_bfloat16 Bh[BN * LDS], Bl[BN * LDS];

    int tid = threadIdx.x;
    int lane = tid & 31, warp = tid >> 5;
    int wm = (warp & 1) << 6;
    int wn = (warp >> 1) << 5;
    int m0, n0;
    if (CAUSAL) { m0 = c_IM36[blockIdx.x] * BM; n0 = c_JN36[blockIdx.x] * BN; }
    else        { m0 = blockIdx.y * BM;         n0 = blockIdx.x * BN; }

    int Keff = K;
    if (clampK) { int kc = m0 + BM; if (kc < Keff) Keff = kc; }

    int lrow = tid >> 3;            // 0..31
    int lcol = (tid & 7) << 2;      // 0..28 step 4

    float acc[4][4][4];
    #pragma unroll
    for (int i = 0; i < 4; i++)
        #pragma unroll
        for (int j = 0; j < 4; j++)
            #pragma unroll
            for (int r = 0; r < 4; r++) acc[i][j][r] = 0.f;

    float4 pa[4], pb[4];
    #pragma unroll
    for (int r = 0; r < 4; r++) {
        int row = lrow + (r << 5);
        pa[r] = *(const float4*)(A + (size_t)(m0 + row) * lda + lcol);
        pb[r] = *(const float4*)(B + (size_t)(n0 + row) * ldb + lcol);
    }

    for (int k0 = 0; k0 < Keff; k0 += BK) {
        __syncthreads();   // previous mma phase done; smem reusable
        #pragma unroll
        for (int r = 0; r < 4; r++) {
            int row = lrow + (r << 5);
            float4 a = pa[r], b = pb[r];
            __nv_bfloat16 hx = __float2bfloat16(a.x), hy = __float2bfloat16(a.y);
            __nv_bfloat16 hz = __float2bfloat16(a.z), hw = __float2bfloat16(a.w);
            __nv_bfloat16* pah = Ah + row * LDS + lcol;
            pah[0] = hx; pah[1] = hy; pah[2] = hz; pah[3] = hw;
            __nv_bfloat16* pal = Al + row * LDS + lcol;
            pal[0] = __float2bfloat16(a.x - __bfloat162float(hx));
            pal[1] = __float2bfloat16(a.y - __bfloat162float(hy));
            pal[2] = __float2bfloat16(a.z - __bfloat162float(hz));
            pal[3] = __float2bfloat16(a.w - __bfloat162float(hw));
            __nv_bfloat16 gx = __float2bfloat16(b.x), gy = __float2bfloat16(b.y);
            __nv_bfloat16 gz = __float2bfloat16(b.z), gw = __float2bfloat16(b.w);
            __nv_bfloat16* pbh = Bh + row * LDS + lcol;
            pbh[0] = gx; pbh[1] = gy; pbh[2] = gz; pbh[3] = gw;
            __nv_bfloat16* pbl = Bl + row * LDS + lcol;
            pbl[0] = __float2bfloat16(b.x - __bfloat162float(gx));
            pbl[1] = __float2bfloat16(b.y - __bfloat162float(gy));
            pbl[2] = __float2bfloat16(b.z - __bfloat162float(gz));
            pbl[3] = __float2bfloat16(b.w - __bfloat162float(gw));
        }
        __syncthreads();

        if (k0 + BK < Keff) {       // issue next tile's LDGs; latency hides under mma
            int kn = k0 + BK;
            #pragma unroll
            for (int r = 0; r < 4; r++) {
                int row = lrow + (r << 5);
                pa[r] = *(const float4*)(A + (size_t)(m0 + row) * lda + kn + lcol);
                pb[r] = *(const float4*)(B + (size_t)(n0 + row) * ldb + kn + lcol);
            }
        }

        #pragma unroll
        for (int kk = 0; kk < BK; kk += 16) {
            #pragma unroll
            for (int pass = 0; pass < 3; pass++) {
                const __nv_bfloat16* As = (pass == 2) ? Al : Ah;
                const __nv_bfloat16* Bs = (pass == 1) ? Bl : Bh;
                unsigned af[4][4], bf[4][2];
                #pragma unroll
                for (int mi = 0; mi < 4; mi++)
                    ldsm_x4(af[mi], As + (wm + (mi << 4) + (lane & 15)) * LDS + kk + ((lane >> 4) << 3));
                #pragma unroll
                for (int ni2 = 0; ni2 < 2; ni2++) {
                    unsigned r4[4];
                    ldsm_x4(r4, Bs + (wn + (ni2 << 4) + ((lane >> 4) << 3) + (lane & 7)) * LDS
                                 + kk + (((lane >> 3) & 1) << 3));
                    bf[ni2 * 2 + 0][0] = r4[0]; bf[ni2 * 2 + 0][1] = r4[1];
                    bf[ni2 * 2 + 1][0] = r4[2]; bf[ni2 * 2 + 1][1] = r4[3];
                }
                #pragma unroll
                for (int mi = 0; mi < 4; mi++)
                    #pragma unroll
                    for (int ni = 0; ni < 4; ni++)
                        mma16816(acc[mi][ni], af[mi], bf[ni]);
            }
        }
    }

    #pragma unroll
    for (int mi = 0; mi < 4; mi++) {
        #pragma unroll
        for (int ni = 0; ni < 4; ni++) {
            int row = m0 + wm + (mi << 4) + (lane >> 2);
            int col = n0 + wn + (ni << 3) + ((lane & 3) << 1);
            *(float2*)(C + (size_t)row * ldc + col) =
                make_float2(acc[mi][ni][0] * alpha, acc[mi][ni][1] * alpha);
            *(float2*)(C + (size_t)(row + 8) * ldc + col) =
                make_float2(acc[mi][ni][2] * alpha, acc[mi][ni][3] * alpha);
        }
    }
}

// ============ 2-pass fp16 GEMM (O projection) with register double-buffer ============
__global__ void __launch_bounds__(256, 2) hgemm2_abT(
    const float* __restrict__ A, int lda,
    const float* __restrict__ B, int ldb,
    float* __restrict__ C, int ldc, int K)
{
    __shared__ __align__(16) __half As[BM * LDS];
    __shared__ __align__(16) __half Bh[BN * LDS], Bl[BN * LDS];

    int tid = threadIdx.x;
    int lane = tid & 31, warp = tid >> 5;
    int wm = (warp & 1) << 6;
    int wn = (warp >> 1) << 5;
    int m0 = blockIdx.y * BM, n0 = blockIdx.x * BN;

    int lrow = tid >> 3, lcol = (tid & 7) << 2;

    float acc[4][4][4];
    #pragma unroll
    for (int i = 0; i < 4; i++)
        #pragma unroll
        for (int j = 0; j < 4; j++)
            #pragma unroll
            for (int r = 0; r < 4; r++) acc[i][j][r] = 0.f;

    float4 pa[4], pb[4];
    #pragma unroll
    for (int r = 0; r < 4; r++) {
        int row = lrow + (r << 5);
        pa[r] = *(const float4*)(A + (size_t)(m0 + row) * lda + lcol);
        pb[r] = *(const float4*)(B + (size_t)(n0 + row) * ldb + lcol);
    }

    for (int k0 = 0; k0 < K; k0 += BK) {
        __syncthreads();
        #pragma unroll
        for (int r = 0; r < 4; r++) {
            int row = lrow + (r << 5);
            float4 a = pa[r], b = pb[r];
            __half* ps = As + row * LDS + lcol;
            ps[0] = __float2half(a.x); ps[1] = __float2half(a.y);
            ps[2] = __float2half(a.z); ps[3] = __float2half(a.w);
            __half hx = __float2half(b.x), hy = __float2half(b.y);
            __half hz = __float2half(b.z), hw = __float2half(b.w);
            __half* pbh = Bh + row * LDS + lcol;
            pbh[0] = hx; pbh[1] = hy; pbh[2] = hz; pbh[3] = hw;
            __half* pbl = Bl + row * LDS + lcol;
            pbl[0] = __float2half(b.x - __half2float(hx));
            pbl[1] = __float2half(b.y - __half2float(hy));
            pbl[2] = __float2half(b.z - __half2float(hz));
            pbl[3] = __float2half(b.w - __half2float(hw));
        }
        __syncthreads();

        if (k0 + BK < K) {
            int kn = k0 + BK;
            #pragma unroll
            for (int r = 0; r < 4; r++) {
                int row = lrow + (r << 5);
                pa[r] = *(const float4*)(A + (size_t)(m0 + row) * lda + kn + lcol);
                pb[r] = *(const float4*)(B + (size_t)(n0 + row) * ldb + kn + lcol);
            }
        }

        #pragma unroll
        for (int kk = 0; kk < BK; kk += 16) {
            unsigned af[4][4];
            #pragma unroll
            for (int mi = 0; mi < 4; mi++)
                ldsm_x4(af[mi], As + (wm + (mi << 4) + (lane & 15)) * LDS + kk + ((lane >> 4) << 3));
            #pragma unroll
            for (int pass = 0; pass < 2; pass++) {
                const __half* Bs = pass ? Bl : Bh;
                unsigned bf[4][2];
                #pragma unroll
                for (int ni2 = 0; ni2 < 2; ni2++) {
                    unsigned r4[4];
                    ldsm_x4(r4, Bs + (wn + (ni2 << 4) + ((lane >> 4) << 3) + (lane & 7)) * LDS
                                 + kk + (((lane >> 3) & 1) << 3));
                    bf[ni2 * 2 + 0][0] = r4[0]; bf[ni2 * 2 + 0][1] = r4[1];
                    bf[ni2 * 2 + 1][0] = r4[2]; bf[ni2 * 2 + 1][1] = r4[3];
                }
                #pragma unroll
                for (int mi = 0; mi < 4; mi++)
                    #pragma unroll
                    for (int ni = 0; ni < 4; ni++)
                        mma16816h(acc[mi][ni], af[mi], bf[ni]);
            }
        }
    }

    #pragma unroll
    for (int mi = 0; mi < 4; mi++) {
        #pragma unroll
        for (int ni = 0; ni < 4; ni++) {
            int row = m0 + wm + (mi << 4) + (lane >> 2);
            int col = n0 + wn + (ni << 3) + ((lane & 3) << 1);
            *(float2*)(C + (size_t)row * ldc + col) =
                make_float2(acc[mi][ni][0], acc[mi][ni][1]);
            *(float2*)(C + (size_t)(row + 8) * ldc + col) =
                make_float2(acc[mi][ni][2], acc[mi][ni][3]);
        }
    }
}

// =============== RoPE (in place) ===============
__global__ void __launch_bounds__(256) rope_kernel(float* __restrict__ X, int nheads,
                            const float* __restrict__ cosb, const float* __restrict__ sinb)
{
    int t = blockIdx.x, tid = threadIdx.x;
    __shared__ float cs[HD], sn[HD];
    if (tid < HD) { cs[tid] = cosb[t * HD + tid]; sn[tid] = sinb[t * HD + tid]; }
    __syncthreads();
    for (int idx = tid; idx < nheads * 64; idx += 256) {
        int h = idx >> 6, d = idx & 63;
        float* p = X + ((size_t)t * nheads + h) * HD;
        float x1 = p[d], x2 = p[d + 64];
        p[d]      = x1 * cs[d]      - x2 * sn[d];
        p[d + 64] = x2 * cs[d + 64] + x1 * sn[d + 64];
    }
}

// =============== V transpose (fp32) ===============
__global__ void transpose_v(const float* __restrict__ V, float* __restrict__ VT)
{
    __shared__ float tile[32][33];
    int kv = blockIdx.z;
    int s0 = blockIdx.x * 32, d0 = blockIdx.y * 32;
    int x = threadIdx.x, y = threadIdx.y;
    #pragma unroll
    for (int i = 0; i < 32; i += 8)
        tile[y + i][x] = V[(size_t)(s0 + y + i) * (NKV * HD) + kv * HD + d0 + x];
    __syncthreads();
    #pragma unroll
    for (int i = 0; i < 32; i += 8)
        VT[(size_t)kv * HD * S_LEN + (size_t)(d0 + y + i) * S_LEN + s0 + x] = tile[x][y + i];
}

// =============== per-row fetch_num ===============
__global__ void __launch_bounds__(256) stats_kernel(const float* __restrict__ P,
                                                    int* __restrict__ fetch)
{
    int t = blockIdx.x, tid = threadIdx.x;
    int len = t + 1;
    __shared__ float sf[256];
    __shared__ int si[256];
    const float* row0 = P + (size_t)t * S_LEN;
    float m = -3.4e38f;
    for (int s = tid; s < len; s += 256) m = fmaxf(m, row0[s]);
    sf[tid] = m; __syncthreads();
    for (int off = 128; off > 0; off >>= 1) { if (tid < off) sf[tid] = fmaxf(sf[tid], sf[tid + off]); __syncthreads(); }
    float thr = sf[0] - 5.0f;
    int cnt = 0;
    for (int h = 0; h < NH; h++) {
        const float* row = P + ((size_t)h * S_LEN + t) * S_LEN;
        for (int s = tid; s < len; s += 256) cnt += (row[s] >= thr) ? 1 : 0;
    }
    si[tid] = cnt; __syncthreads();
    for (int off = 128; off > 0; off >>= 1) { if (tid < off) si[tid] += si[tid + off]; __syncthreads(); }
    if (tid == 0) {
        int f = si[0] >> 5;
        fetch[t] = f < FETCH_MAX ? f : FETCH_MAX;
    }
}

__device__ __forceinline__ unsigned fkey(float f) {
    unsigned u = __float_as_uint(f);
    return (u & 0x80000000u) ? ~u : (u | 0x80000000u);
}

// ====== fused radix-select top-k + softmax (probs in place, fp32) ======
__global__ void __launch_bounds__(256) softmax_select(float* __restrict__ P,
                                                      const int* __restrict__ fetch,
                                                      const float* __restrict__ Q,
                                                      const float* __restrict__ Kf)
{
    int t = blockIdx.x, h = blockIdx.y, tid = threadIdx.x;
    float* row = P + ((size_t)h * S_LEN + t) * S_LEN;
    __shared__ float srow[S_LEN];
    __shared__ float sf[256];
    __shared__ unsigned hist[256];
    __shared__ unsigned s_sel;
    __shared__ int s_kk, s_cut;

    int len = t + 1;
    bool do_topk = false;
    int k = 0;
    if (t >= FETCH_MAX) {
        k = fetch[t];
        if (k == 0) len = S_LEN;
        else do_topk = true;
    }

    for (int s = tid; s < t + 1; s += 256) srow[s] = row[s];
    if (len == S_LEN && t + 1 < S_LEN) {
        const float* qp = Q + (size_t)t * D_DIM + h * HD;
        int kv = h >> 2;
        for (int s = t + 1 + tid; s < S_LEN; s += 256) {
            const float* kp = Kf + (size_t)s * (NKV * HD) + kv * HD;
            float a = 0.f;
            #pragma unroll 8
            for (int d = 0; d < HD; d++) a += qp[d] * kp[d];
            srow[s] = a * 0.08838834764831845f;
        }
    }
    __syncthreads();

    float m = -3.4e38f;
    for (int s = tid; s < len; s += 256) m = fmaxf(m, srow[s]);
    sf[tid] = m; __syncthreads();
    for (int off = 128; off > 0; off >>= 1) { if (tid < off) sf[tid] = fmaxf(sf[tid], sf[tid + off]); __syncthreads(); }
    float rowmax = sf[0];
    __syncthreads();

    unsigned uthr = 0;
    int cut = len;
    if (do_topk) {
        unsigned prefix = 0, pmask = 0;
        int kk = k;
        for (int shift = 24; shift >= 0; shift -= 8) {
            hist[tid] = 0; __syncthreads();
            for (int s = tid; s < len; s += 256) {
                unsigned u = fkey(srow[s]);
                if ((u & pmask) == prefix) atomicAdd(&hist[(u >> shift) & 255u], 1u);
            }
            __syncthreads();
            if (tid == 0) {
                int rem = kk; int b = 255;
                for (; b > 0; b--) { int c = (int)hist[b]; if (rem <= c) break; rem -= c; }
                s_sel = (unsigned)b; s_kk = rem;
            }
            __syncthreads();
            prefix |= (s_sel << shift);
            pmask  |= (0xFFu << shift);
            kk = s_kk;
            __syncthreads();
        }
        uthr = prefix;
        int e = 0;
        for (int s = tid; s < len; s += 256) if (fkey(srow[s]) == uthr) e++;
        hist[tid] = (unsigned)e; __syncthreads();
        for (int off = 128; off > 0; off >>= 1) { if (tid < off) hist[tid] += hist[tid + off]; __syncthreads(); }
        int E = (int)hist[0];
        __syncthreads();
        if (E != kk) {
            if (tid == 0) {
                int c = 0, ci = -1;
                for (int s = 0; s < len; s++)
                    if (fkey(srow[s]) == uthr) { c++; if (c == kk) { ci = s; break; } }
                s_cut = ci;
            }
            __syncthreads();
            cut = s_cut;
        }
    }

    float z = 0.f;
    for (int s = tid; s < len; s += 256) {
        float x = srow[s];
        bool keep = true;
        if (do_topk) {
            unsigned u = fkey(x);
            keep = (u > uthr) || (u == uthr && s <= cut);
        }
        if (keep) z += expf(x - rowmax);
    }
    sf[tid] = z; __syncthreads();
    for (int off = 128; off > 0; off >>= 1) { if (tid < off) sf[tid] += sf[tid + off]; __syncthreads(); }
    float inv = 1.0f / sf[0];
    __syncthreads();

    for (int s = tid; s < S_LEN; s += 256) {
        float p = 0.f;
        if (s < len) {
            float x = srow[s];
            bool keep = true;
            if (do_topk) {
                unsigned u = fkey(x);
                keep = (u > uthr) || (u == uthr && s <= cut);
            }
            if (keep) p = expf(x - rowmax) * inv;
        }
        row[s] = p;
    }
}

extern "C" void kernel_launch(void* const* d_in, const int* in_sizes, int n_in,
                              void* d_out, int out_size)
{
    const float* hidden = (const float*)d_in[0];
    const float* cosb   = (const float*)d_in[1];
    const float* sinb   = (const float*)d_in[2];
    const float* Wq     = (const float*)d_in[3];
    const float* Wk     = (const float*)d_in[4];
    const float* Wv     = (const float*)d_in[5];
    const float* Wo     = (const float*)d_in[6];
    float* out = (float*)d_out;

    float *Q, *K, *V, *VT, *P, *AO; int* F;
    cudaGetSymbolAddress((void**)&Q,  g_Q);
    cudaGetSymbolAddress((void**)&K,  g_K);
    cudaGetSymbolAddress((void**)&V,  g_V);
    cudaGetSymbolAddress((void**)&VT, g_VT);
    cudaGetSymbolAddress((void**)&P,  g_P);
    cudaGetSymbolAddress((void**)&AO, g_AO);
    cudaGetSymbolAddress((void**)&F,  g_fetch);

    const float scale = 0.08838834764831845f; // 1/sqrt(128)
    dim3 blk(256);

    // Projections: X @ W^T  (3-pass split bf16, reg double-buffered)
    bgemm_abT<0><<<dim3(D_DIM / BN, S_LEN / BM, 1), blk>>>(
        hidden, D_DIM, 0, Wq, D_DIM, 0, 1, Q, D_DIM, 0, D_DIM, 1.f, 0);
    bgemm_abT<0><<<dim3((NKV * HD) / BN, S_LEN / BM, 1), blk>>>(
        hidden, D_DIM, 0, Wk, D_DIM, 0, 1, K, NKV * HD, 0, D_DIM, 1.f, 0);
    bgemm_abT<0><<<dim3((NKV * HD) / BN, S_LEN / BM, 1), blk>>>(
        hidden, D_DIM, 0, Wv, D_DIM, 0, 1, V, NKV * HD, 0, D_DIM, 1.f, 0);

    rope_kernel<<<S_LEN, 256>>>(Q, NH,  cosb, sinb);
    rope_kernel<<<S_LEN, 256>>>(K, NKV, cosb, sinb);
    transpose_v<<<dim3(S_LEN / 32, HD / 32, NKV), dim3(32, 8)>>>(V, VT);

    // Scores: causal lower-triangle blocks only (36 of 64 per head)
    bgemm_abT<1><<<dim3(36, 1, NH), blk>>>(
        Q, D_DIM, HD, K, NKV * HD, HD, 4,
        P, S_LEN, (long long)S_LEN * S_LEN, HD, scale, 0);

    stats_kernel<<<S_LEN, 256>>>(P, F);
    softmax_select<<<dim3(S_LEN, NH), 256>>>(P, F, Q, K);

    // PV: P_h @ VT_kv^T with causal K clamp
    bgemm_abT<0><<<dim3(HD / BN, S_LEN / BM, NH), blk>>>(
        P, S_LEN, (long long)S_LEN * S_LEN, VT, S_LEN, (long long)HD * S_LEN, 4,
        AO, D_DIM, HD, S_LEN, 1.f, 1);

    // Output projection: AO @ Wo^T  (2-pass fp16, reg double-buffered)
    hgemm2_abT<<<dim3(D_DIM / BN, S_LEN / BM, 1), blk>>>(
        AO, D_DIM, Wo, D_DIM, out, D_DIM, D_DIM);

    (void)in_sizes; (void)n_in; (void)out_size;
}

// round 8
// speedup vs baseline: 1.2292x; 1.2292x over previous
#include <cuda_runtime.h>
#include <cuda_bf16.h>
#include <cuda_fp16.h>
#include <stdint.h>
#include <math.h>

#define S_LEN 1024
#define D_DIM 4096
#define NH 32
#define NKV 8
#define HD 128
#define FETCH_MAX 204

#define BM 128
#define BN 128
#define BK 32
#define LDS 40                 // padded 16-bit element stride (80B, 16B-aligned)
#define TILE (128 * LDS)
#define STAGE4 (4 * TILE)      // 3-pass kernel: Ah,Al,Bh,Bl
#define STAGE3 (3 * TILE)      // 2-pass kernel: Ah,Bh,Bl
#define SMEM4 (2 * STAGE4 * 2)
#define SMEM3 (2 * STAGE3 * 2)

// -------- scratch (device globals) --------
__device__ float g_Q[(size_t)S_LEN * D_DIM];
__device__ float g_K[(size_t)S_LEN * NKV * HD];
__device__ float g_V[(size_t)S_LEN * NKV * HD];
__device__ float g_P[(size_t)NH * S_LEN * S_LEN];
__device__ float g_AO[(size_t)S_LEN * D_DIM];
__device__ int   g_fetch[S_LEN];

__device__ __nv_bfloat16 g_hidH[(size_t)S_LEN * D_DIM],      g_hidL[(size_t)S_LEN * D_DIM];
__device__ __nv_bfloat16 g_WqH[(size_t)D_DIM * D_DIM],       g_WqL[(size_t)D_DIM * D_DIM];
__device__ __nv_bfloat16 g_WkH[(size_t)NKV * HD * D_DIM],    g_WkL[(size_t)NKV * HD * D_DIM];
__device__ __nv_bfloat16 g_WvH[(size_t)NKV * HD * D_DIM],    g_WvL[(size_t)NKV * HD * D_DIM];
__device__ __nv_bfloat16 g_QH[(size_t)S_LEN * D_DIM],        g_QL[(size_t)S_LEN * D_DIM];
__device__ __nv_bfloat16 g_KH[(size_t)S_LEN * NKV * HD],     g_KL[(size_t)S_LEN * NKV * HD];
__device__ __nv_bfloat16 g_VTH[(size_t)NKV * HD * S_LEN],    g_VTL[(size_t)NKV * HD * S_LEN];
__device__ __nv_bfloat16 g_PH[(size_t)NH * S_LEN * S_LEN],   g_PL[(size_t)NH * S_LEN * S_LEN];
__device__ __half        g_WoH[(size_t)D_DIM * D_DIM],       g_WoL[(size_t)D_DIM * D_DIM];
__device__ __half        g_AOH[(size_t)S_LEN * D_DIM];

// lower-triangle 128x128 block map (8x8 grid -> 36 blocks)
__constant__ int c_IM36[36] = {0,1,1,2,2,2,3,3,3,3,4,4,4,4,4,5,5,5,5,5,5,
                               6,6,6,6,6,6,6,7,7,7,7,7,7,7,7};
__constant__ int c_JN36[36] = {0,0,1,0,1,2,0,1,2,3,0,1,2,3,4,0,1,2,3,4,5,
                               0,1,2,3,4,5,6,0,1,2,3,4,5,6,7};

// ---------------- primitives ----------------
__device__ __forceinline__ void ldsm_x4(unsigned r[4], const void* p) {
    unsigned a = (unsigned)__cvta_generic_to_shared(p);
    asm volatile("ldmatrix.sync.aligned.m8n8.x4.shared.b16 {%0,%1,%2,%3}, [%4];"
                 : "=r"(r[0]), "=r"(r[1]), "=r"(r[2]), "=r"(r[3]) : "r"(a));
}
__device__ __forceinline__ void mma16816(float* d, const unsigned* a, const unsigned* b) {
    asm volatile("mma.sync.aligned.m16n8k16.row.col.f32.bf16.bf16.f32 "
                 "{%0,%1,%2,%3}, {%4,%5,%6,%7}, {%8,%9}, {%0,%1,%2,%3};"
                 : "+f"(d[0]), "+f"(d[1]), "+f"(d[2]), "+f"(d[3])
                 : "r"(a[0]), "r"(a[1]), "r"(a[2]), "r"(a[3]), "r"(b[0]), "r"(b[1]));
}
__device__ __forceinline__ void mma16816h(float* d, const unsigned* a, const unsigned* b) {
    asm volatile("mma.sync.aligned.m16n8k16.row.col.f32.f16.f16.f32 "
                 "{%0,%1,%2,%3}, {%4,%5,%6,%7}, {%8,%9}, {%0,%1,%2,%3};"
                 : "+f"(d[0]), "+f"(d[1]), "+f"(d[2]), "+f"(d[3])
                 : "r"(a[0]), "r"(a[1]), "r"(a[2]), "r"(a[3]), "r"(b[0]), "r"(b[1]));
}
__device__ __forceinline__ void cpasync16(void* smem, const void* g) {
    unsigned s = (unsigned)__cvta_generic_to_shared(smem);
    asm volatile("cp.async.cg.shared.global [%0], [%1], 16;" :: "r"(s), "l"(g));
}
__device__ __forceinline__ void cp_commit() { asm volatile("cp.async.commit_group;"); }
template <int N> __device__ __forceinline__ void cp_wait() {
    asm volatile("cp.async.wait_group %0;" :: "n"(N) : "memory");
}

// ============ cp.async split-bf16 GEMM (3-pass): C = alpha * A @ B^T ============
template <int CAUSAL>
__global__ void __launch_bounds__(256) bgemm3(
    const __nv_bfloat16* __restrict__ Ah, const __nv_bfloat16* __restrict__ Al,
    int lda, long long sA,
    const __nv_bfloat16* __restrict__ Bh, const __nv_bfloat16* __restrict__ Bl,
    int ldb, long long sB, int zdivB,
    float* __restrict__ C, int ldc, long long sC,
    int K, float alpha, int clampK)
{
    long long za = (long long)blockIdx.z * sA;
    long long zb = (long long)(blockIdx.z / zdivB) * sB;
    C += (long long)blockIdx.z * sC;

    extern __shared__ __nv_bfloat16 smem[];

    int tid = threadIdx.x;
    int lane = tid & 31, warp = tid >> 5;
    int wm = (warp & 1) << 6;
    int wn = (warp >> 1) << 5;
    int m0, n0;
    if (CAUSAL) { m0 = c_IM36[blockIdx.x] * BM; n0 = c_JN36[blockIdx.x] * BN; }
    else        { m0 = blockIdx.y * BM;         n0 = blockIdx.x * BN; }

    int Keff = K;
    if (clampK) { int kc = m0 + BM; if (kc < Keff) Keff = kc; }

    const __nv_bfloat16* gA0 = Ah + za + (size_t)m0 * lda;
    const __nv_bfloat16* gA1 = Al + za + (size_t)m0 * lda;
    const __nv_bfloat16* gB0 = Bh + zb + (size_t)n0 * ldb;
    const __nv_bfloat16* gB1 = Bl + zb + (size_t)n0 * ldb;

    int w0 = tid, w1 = tid + 256;
    int r0 = w0 >> 2, c0 = (w0 & 3) << 3;
    int r1 = w1 >> 2, c1 = (w1 & 3) << 3;

    float acc[4][4][4];
    #pragma unroll
    for (int i = 0; i < 4; i++)
        #pragma unroll
        for (int j = 0; j < 4; j++)
            #pragma unroll
            for (int r = 0; r < 4; r++) acc[i][j][r] = 0.f;

    auto load_stage = [&](int st, int k0) {
        __nv_bfloat16* s = smem + st * STAGE4;
        cpasync16(s + 0*TILE + r0*LDS + c0, gA0 + (size_t)r0*lda + k0 + c0);
        cpasync16(s + 0*TILE + r1*LDS + c1, gA0 + (size_t)r1*lda + k0 + c1);
        cpasync16(s + 1*TILE + r0*LDS + c0, gA1 + (size_t)r0*lda + k0 + c0);
        cpasync16(s + 1*TILE + r1*LDS + c1, gA1 + (size_t)r1*lda + k0 + c1);
        cpasync16(s + 2*TILE + r0*LDS + c0, gB0 + (size_t)r0*ldb + k0 + c0);
        cpasync16(s + 2*TILE + r1*LDS + c1, gB0 + (size_t)r1*ldb + k0 + c1);
        cpasync16(s + 3*TILE + r0*LDS + c0, gB1 + (size_t)r0*ldb + k0 + c0);
        cpasync16(s + 3*TILE + r1*LDS + c1, gB1 + (size_t)r1*ldb + k0 + c1);
        cp_commit();
    };

    int nk = Keff / BK;
    load_stage(0, 0);

    for (int it = 0; it < nk; it++) {
        int st = it & 1;
        if (it + 1 < nk) { load_stage(st ^ 1, (it + 1) * BK); cp_wait<1>(); }
        else             { cp_wait<0>(); }
        __syncthreads();

        const __nv_bfloat16* Ah_s = smem + st * STAGE4;
        const __nv_bfloat16* Al_s = Ah_s + TILE;
        const __nv_bfloat16* Bh_s = Ah_s + 2 * TILE;
        const __nv_bfloat16* Bl_s = Ah_s + 3 * TILE;

        #pragma unroll
        for (int kk = 0; kk < BK; kk += 16) {
            unsigned af[4][4], bf[4][2];
            #pragma unroll
            for (int mi = 0; mi < 4; mi++)
                ldsm_x4(af[mi], Ah_s + (wm + (mi << 4) + (lane & 15)) * LDS + kk + ((lane >> 4) << 3));
            #pragma unroll
            for (int ni2 = 0; ni2 < 2; ni2++) {
                unsigned r4[4];
                ldsm_x4(r4, Bh_s + (wn + (ni2 << 4) + ((lane >> 4) << 3) + (lane & 7)) * LDS
                             + kk + (((lane >> 3) & 1) << 3));
                bf[ni2*2+0][0] = r4[0]; bf[ni2*2+0][1] = r4[1];
                bf[ni2*2+1][0] = r4[2]; bf[ni2*2+1][1] = r4[3];
            }
            #pragma unroll
            for (int mi = 0; mi < 4; mi++)
                #pragma unroll
                for (int ni = 0; ni < 4; ni++)
                    mma16816(acc[mi][ni], af[mi], bf[ni]);     // hi*hi

            #pragma unroll
            for (int ni2 = 0; ni2 < 2; ni2++) {
                unsigned r4[4];
                ldsm_x4(r4, Bl_s + (wn + (ni2 << 4) + ((lane >> 4) << 3) + (lane & 7)) * LDS
                             + kk + (((lane >> 3) & 1) << 3));
                bf[ni2*2+0][0] = r4[0]; bf[ni2*2+0][1] = r4[1];
                bf[ni2*2+1][0] = r4[2]; bf[ni2*2+1][1] = r4[3];
            }
            #pragma unroll
            for (int mi = 0; mi < 4; mi++)
                #pragma unroll
                for (int ni = 0; ni < 4; ni++)
                    mma16816(acc[mi][ni], af[mi], bf[ni]);     // hi*lo

            #pragma unroll
            for (int mi = 0; mi < 4; mi++)
                ldsm_x4(af[mi], Al_s + (wm + (mi << 4) + (lane & 15)) * LDS + kk + ((lane >> 4) << 3));
            #pragma unroll
            for (int ni2 = 0; ni2 < 2; ni2++) {
                unsigned r4[4];
                ldsm_x4(r4, Bh_s + (wn + (ni2 << 4) + ((lane >> 4) << 3) + (lane & 7)) * LDS
                             + kk + (((lane >> 3) & 1) << 3));
                bf[ni2*2+0][0] = r4[0]; bf[ni2*2+0][1] = r4[1];
                bf[ni2*2+1][0] = r4[2]; bf[ni2*2+1][1] = r4[3];
            }
            #pragma unroll
            for (int mi = 0; mi < 4; mi++)
                #pragma unroll
                for (int ni = 0; ni < 4; ni++)
                    mma16816(acc[mi][ni], af[mi], bf[ni]);     // lo*hi
        }
        __syncthreads();
    }

    #pragma unroll
    for (int mi = 0; mi < 4; mi++) {
        #pragma unroll
        for (int ni = 0; ni < 4; ni++) {
            int row = m0 + wm + (mi << 4) + (lane >> 2);
            int col = n0 + wn + (ni << 3) + ((lane & 3) << 1);
            *(float2*)(C + (size_t)row * ldc + col) =
                make_float2(acc[mi][ni][0] * alpha, acc[mi][ni][1] * alpha);
            *(float2*)(C + (size_t)(row + 8) * ldc + col) =
                make_float2(acc[mi][ni][2] * alpha, acc[mi][ni][3] * alpha);
        }
    }
}

// ============ cp.async fp16 2-pass GEMM: C = Ah @ (Bh + Bl)^T ============
__global__ void __launch_bounds__(256) hgemm2(
    const __half* __restrict__ Ah, int lda,
    const __half* __restrict__ Bh, const __half* __restrict__ Bl, int ldb,
    float* __restrict__ C, int ldc, int K)
{
    extern __shared__ __half smh[];

    int tid = threadIdx.x;
    int lane = tid & 31, warp = tid >> 5;
    int wm = (warp & 1) << 6;
    int wn = (warp >> 1) << 5;
    int m0 = blockIdx.y * BM, n0 = blockIdx.x * BN;

    const __half* gA = Ah + (size_t)m0 * lda;
    const __half* gB0 = Bh + (size_t)n0 * ldb;
    const __half* gB1 = Bl + (size_t)n0 * ldb;

    int w0 = tid, w1 = tid + 256;
    int r0 = w0 >> 2, c0 = (w0 & 3) << 3;
    int r1 = w1 >> 2, c1 = (w1 & 3) << 3;

    float acc[4][4][4];
    #pragma unroll
    for (int i = 0; i < 4; i++)
        #pragma unroll
        for (int j = 0; j < 4; j++)
            #pragma unroll
            for (int r = 0; r < 4; r++) acc[i][j][r] = 0.f;

    auto load_stage = [&](int st, int k0) {
        __half* s = smh + st * STAGE3;
        cpasync16(s + 0*TILE + r0*LDS + c0, gA  + (size_t)r0*lda + k0 + c0);
        cpasync16(s + 0*TILE + r1*LDS + c1, gA  + (size_t)r1*lda + k0 + c1);
        cpasync16(s + 1*TILE + r0*LDS + c0, gB0 + (size_t)r0*ldb + k0 + c0);
        cpasync16(s + 1*TILE + r1*LDS + c1, gB0 + (size_t)r1*ldb + k0 + c1);
        cpasync16(s + 2*TILE + r0*LDS + c0, gB1 + (size_t)r0*ldb + k0 + c0);
        cpasync16(s + 2*TILE + r1*LDS + c1, gB1 + (size_t)r1*ldb + k0 + c1);
        cp_commit();
    };

    int nk = K / BK;
    load_stage(0, 0);

    for (int it = 0; it < nk; it++) {
        int st = it & 1;
        if (it + 1 < nk) { load_stage(st ^ 1, (it + 1) * BK); cp_wait<1>(); }
        else             { cp_wait<0>(); }
        __syncthreads();

        const __half* As = smh + st * STAGE3;
        const __half* Bhs = As + TILE;
        const __half* Bls = As + 2 * TILE;

        #pragma unroll
        for (int kk = 0; kk < BK; kk += 16) {
            unsigned af[4][4];
            #pragma unroll
            for (int mi = 0; mi < 4; mi++)
                ldsm_x4(af[mi], As + (wm + (mi << 4) + (lane & 15)) * LDS + kk + ((lane >> 4) << 3));
            #pragma unroll
            for (int pass = 0; pass < 2; pass++) {
                const __half* Bs = pass ? Bls : Bhs;
                unsigned bf[4][2];
                #pragma unroll
                for (int ni2 = 0; ni2 < 2; ni2++) {
                    unsigned r4[4];
                    ldsm_x4(r4, Bs + (wn + (ni2 << 4) + ((lane >> 4) << 3) + (lane & 7)) * LDS
                                 + kk + (((lane >> 3) & 1) << 3));
                    bf[ni2*2+0][0] = r4[0]; bf[ni2*2+0][1] = r4[1];
                    bf[ni2*2+1][0] = r4[2]; bf[ni2*2+1][1] = r4[3];
                }
                #pragma unroll
                for (int mi = 0; mi < 4; mi++)
                    #pragma unroll
                    for (int ni = 0; ni < 4; ni++)
                        mma16816h(acc[mi][ni], af[mi], bf[ni]);
            }
        }
        __syncthreads();
    }

    #pragma unroll
    for (int mi = 0; mi < 4; mi++) {
        #pragma unroll
        for (int ni = 0; ni < 4; ni++) {
            int row = m0 + wm + (mi << 4) + (lane >> 2);
            int col = n0 + wn + (ni << 3) + ((lane & 3) << 1);
            *(float2*)(C + (size_t)row * ldc + col) =
                make_float2(acc[mi][ni][0], acc[mi][ni][1]);
            *(float2*)(C + (size_t)(row + 8) * ldc + col) =
                make_float2(acc[mi][ni][2], acc[mi][ni][3]);
        }
    }
}

// =============== splits ===============
__device__ __forceinline__ unsigned pk2b(__nv_bfloat16 a, __nv_bfloat16 b) {
    unsigned short ua = *(unsigned short*)&a, ub = *(unsigned short*)&b;
    return (unsigned)ua | ((unsigned)ub << 16);
}
__global__ void __launch_bounds__(256) split_f32(const float4* __restrict__ X,
                                                 uint2* __restrict__ H,
                                                 uint2* __restrict__ L, int n4)
{
    int i = blockIdx.x * 256 + threadIdx.x;
    if (i >= n4) return;
    float4 v = X[i];
    __nv_bfloat16 h0 = __float2bfloat16(v.x), h1 = __float2bfloat16(v.y);
    __nv_bfloat16 h2 = __float2bfloat16(v.z), h3 = __float2bfloat16(v.w);
    H[i] = make_uint2(pk2b(h0, h1), pk2b(h2, h3));
    L[i] = make_uint2(
        pk2b(__float2bfloat16(v.x - __bfloat162float(h0)), __float2bfloat16(v.y - __bfloat162float(h1))),
        pk2b(__float2bfloat16(v.z - __bfloat162float(h2)), __float2bfloat16(v.w - __bfloat162float(h3))));
}
__device__ __forceinline__ unsigned pk2h(__half a, __half b) {
    unsigned short ua = *(unsigned short*)&a, ub = *(unsigned short*)&b;
    return (unsigned)ua | ((unsigned)ub << 16);
}
__global__ void __launch_bounds__(256) split_h_hl(const float4* __restrict__ X,
                                                  uint2* __restrict__ H,
                                                  uint2* __restrict__ L, int n4)
{
    int i = blockIdx.x * 256 + threadIdx.x;
    if (i >= n4) return;
    float4 v = X[i];
    __half h0 = __float2half(v.x), h1 = __float2half(v.y);
    __half h2 = __float2half(v.z), h3 = __float2half(v.w);
    H[i] = make_uint2(pk2h(h0, h1), pk2h(h2, h3));
    L[i] = make_uint2(
        pk2h(__float2half(v.x - __half2float(h0)), __float2half(v.y - __half2float(h1))),
        pk2h(__float2half(v.z - __half2float(h2)), __float2half(v.w - __half2float(h3))));
}
__global__ void __launch_bounds__(256) split_h_h(const float4* __restrict__ X,
                                                 uint2* __restrict__ H, int n4)
{
    int i = blockIdx.x * 256 + threadIdx.x;
    if (i >= n4) return;
    float4 v = X[i];
    H[i] = make_uint2(pk2h(__float2half(v.x), __float2half(v.y)),
                      pk2h(__float2half(v.z), __float2half(v.w)));
}

// =============== RoPE ===============
__global__ void __launch_bounds__(256) rope_kernel(float* __restrict__ X, int nheads,
                            const float* __restrict__ cosb, const float* __restrict__ sinb)
{
    int t = blockIdx.x, tid = threadIdx.x;
    __shared__ float cs[HD], sn[HD];
    if (tid < HD) { cs[tid] = cosb[t * HD + tid]; sn[tid] = sinb[t * HD + tid]; }
    __syncthreads();
    for (int idx = tid; idx < nheads * 64; idx += 256) {
        int h = idx >> 6, d = idx & 63;
        float* p = X + ((size_t)t * nheads + h) * HD;
        float x1 = p[d], x2 = p[d + 64];
        p[d]      = x1 * cs[d]      - x2 * sn[d];
        p[d + 64] = x2 * cs[d + 64] + x1 * sn[d + 64];
    }
}

// ========= V transpose + split =========
__global__ void transpose_v(const float* __restrict__ V,
                            __nv_bfloat16* __restrict__ VTH, __nv_bfloat16* __restrict__ VTL)
{
    __shared__ float tile[32][33];
    int kv = blockIdx.z;
    int s0 = blockIdx.x * 32, d0 = blockIdx.y * 32;
    int x = threadIdx.x, y = threadIdx.y;
    #pragma unroll
    for (int i = 0; i < 32; i += 8)
        tile[y + i][x] = V[(size_t)(s0 + y + i) * (NKV * HD) + kv * HD + d0 + x];
    __syncthreads();
    #pragma unroll
    for (int i = 0; i < 32; i += 8) {
        float v = tile[x][y + i];
        __nv_bfloat16 h = __float2bfloat16(v);
        size_t o = (size_t)kv * HD * S_LEN + (size_t)(d0 + y + i) * S_LEN + s0 + x;
        VTH[o] = h;
        VTL[o] = __float2bfloat16(v - __bfloat162float(h));
    }
}

// =============== per-row fetch_num ===============
__global__ void __launch_bounds__(256) stats_kernel(const float* __restrict__ P,
                                                    int* __restrict__ fetch)
{
    int t = blockIdx.x, tid = threadIdx.x;
    int len = t + 1;
    __shared__ float sf[256];
    __shared__ int si[256];
    const float* row0 = P + (size_t)t * S_LEN;
    float m = -3.4e38f;
    for (int s = tid; s < len; s += 256) m = fmaxf(m, row0[s]);
    sf[tid] = m; __syncthreads();
    for (int off = 128; off > 0; off >>= 1) { if (tid < off) sf[tid] = fmaxf(sf[tid], sf[tid + off]); __syncthreads(); }
    float thr = sf[0] - 5.0f;
    int cnt = 0;
    for (int h = 0; h < NH; h++) {
        const float* row = P + ((size_t)h * S_LEN + t) * S_LEN;
        for (int s = tid; s < len; s += 256) cnt += (row[s] >= thr) ? 1 : 0;
    }
    si[tid] = cnt; __syncthreads();
    for (int off = 128; off > 0; off >>= 1) { if (tid < off) si[tid] += si[tid + off]; __syncthreads(); }
    if (tid == 0) {
        int f = si[0] >> 5;
        fetch[t] = f < FETCH_MAX ? f : FETCH_MAX;
    }
}

__device__ __forceinline__ unsigned fkey(float f) {
    unsigned u = __float_as_uint(f);
    return (u & 0x80000000u) ? ~u : (u | 0x80000000u);
}

// ====== fused radix-select top-k + softmax -> split bf16 probs ======
__global__ void __launch_bounds__(256) softmax_select(const float* __restrict__ P,
                                                      const int* __restrict__ fetch,
                                                      const float* __restrict__ Q,
                                                      const float* __restrict__ Kf,
                                                      __nv_bfloat16* __restrict__ PH,
                                                      __nv_bfloat16* __restrict__ PL)
{
    int t = blockIdx.x, h = blockIdx.y, tid = threadIdx.x;
    const float* row = P + ((size_t)h * S_LEN + t) * S_LEN;
    __nv_bfloat16* ph = PH + ((size_t)h * S_LEN + t) * S_LEN;
    __nv_bfloat16* pl = PL + ((size_t)h * S_LEN + t) * S_LEN;
    __shared__ float srow[S_LEN];
    __shared__ float sf[256];
    __shared__ unsigned hist[256];
    __shared__ unsigned s_sel;
    __shared__ int s_kk, s_cut;

    int len = t + 1;
    bool do_topk = false;
    int k = 0;
    if (t >= FETCH_MAX) {
        k = fetch[t];
        if (k == 0) len = S_LEN;
        else do_topk = true;
    }

    for (int s = tid; s < t + 1; s += 256) srow[s] = row[s];
    if (len == S_LEN && t + 1 < S_LEN) {
        const float* qp = Q + (size_t)t * D_DIM + h * HD;
        int kv = h >> 2;
        for (int s = t + 1 + tid; s < S_LEN; s += 256) {
            const float* kp = Kf + (size_t)s * (NKV * HD) + kv * HD;
            float a = 0.f;
            #pragma unroll 8
            for (int d = 0; d < HD; d++) a += qp[d] * kp[d];
            srow[s] = a * 0.08838834764831845f;
        }
    }
    __syncthreads();

    float m = -3.4e38f;
    for (int s = tid; s < len; s += 256) m = fmaxf(m, srow[s]);
    sf[tid] = m; __syncthreads();
    for (int off = 128; off > 0; off >>= 1) { if (tid < off) sf[tid] = fmaxf(sf[tid], sf[tid + off]); __syncthreads(); }
    float rowmax = sf[0];
    __syncthreads();

    unsigned uthr = 0;
    int cut = len;
    if (do_topk) {
        unsigned prefix = 0, pmask = 0;
        int kk = k;
        for (int shift = 24; shift >= 0; shift -= 8) {
            hist[tid] = 0; __syncthreads();
            for (int s = tid; s < len; s += 256) {
                unsigned u = fkey(srow[s]);
                if ((u & pmask) == prefix) atomicAdd(&hist[(u >> shift) & 255u], 1u);
            }
            __syncthreads();
            if (tid == 0) {
                int rem = kk; int b = 255;
                for (; b > 0; b--) { int c = (int)hist[b]; if (rem <= c) break; rem -= c; }
                s_sel = (unsigned)b; s_kk = rem;
            }
            __syncthreads();
            prefix |= (s_sel << shift);
            pmask  |= (0xFFu << shift);
            kk = s_kk;
            __syncthreads();
        }
        uthr = prefix;
        int e = 0;
        for (int s = tid; s < len; s += 256) if (fkey(srow[s]) == uthr) e++;
        hist[tid] = (unsigned)e; __syncthreads();
        for (int off = 128; off > 0; off >>= 1) { if (tid < off) hist[tid] += hist[tid + off]; __syncthreads(); }
        int E = (int)hist[0];
        __syncthreads();
        if (E != kk) {
            if (tid == 0) {
                int c = 0, ci = -1;
                for (int s = 0; s < len; s++)
                    if (fkey(srow[s]) == uthr) { c++; if (c == kk) { ci = s; break; } }
                s_cut = ci;
            }
            __syncthreads();
            cut = s_cut;
        }
    }

    float z = 0.f;
    for (int s = tid; s < len; s += 256) {
        float x = srow[s];
        bool keep = true;
        if (do_topk) {
            unsigned u = fkey(x);
            keep = (u > uthr) || (u == uthr && s <= cut);
        }
        if (keep) z += expf(x - rowmax);
    }
    sf[tid] = z; __syncthreads();
    for (int off = 128; off > 0; off >>= 1) { if (tid < off) sf[tid] += sf[tid + off]; __syncthreads(); }
    float inv = 1.0f / sf[0];
    __syncthreads();

    for (int s = tid; s < S_LEN; s += 256) {
        float p = 0.f;
        if (s < len) {
            float x = srow[s];
            bool keep = true;
            if (do_topk) {
                unsigned u = fkey(x);
                keep = (u > uthr) || (u == uthr && s <= cut);
            }
            if (keep) p = expf(x - rowmax) * inv;
        }
        __nv_bfloat16 hp = __float2bfloat16(p);
        ph[s] = hp;
        pl[s] = __float2bfloat16(p - __bfloat162float(hp));
    }
}

static void split_arr(const float* X, __nv_bfloat16* H, __nv_bfloat16* L, size_t n) {
    int n4 = (int)(n / 4);
    split_f32<<<(n4 + 255) / 256, 256>>>((const float4*)X, (uint2*)H, (uint2*)L, n4);
}

extern "C" void kernel_launch(void* const* d_in, const int* in_sizes, int n_in,
                              void* d_out, int out_size)
{
    const float* hidden = (const float*)d_in[0];
    const float* cosb   = (const float*)d_in[1];
    const float* sinb   = (const float*)d_in[2];
    const float* Wq     = (const float*)d_in[3];
    const float* Wk     = (const float*)d_in[4];
    const float* Wv     = (const float*)d_in[5];
    const float* Wo     = (const float*)d_in[6];
    float* out = (float*)d_out;

    static int cfg = 0;
    if (!cfg) {
        cudaFuncSetAttribute(bgemm3<0>, cudaFuncAttributeMaxDynamicSharedMemorySize, SMEM4);
        cudaFuncSetAttribute(bgemm3<1>, cudaFuncAttributeMaxDynamicSharedMemorySize, SMEM4);
        cudaFuncSetAttribute(hgemm2,    cudaFuncAttributeMaxDynamicSharedMemorySize, SMEM3);
        cfg = 1;
    }

    float *Q, *K, *V, *P, *AO; int* F;
    cudaGetSymbolAddress((void**)&Q,  g_Q);
    cudaGetSymbolAddress((void**)&K,  g_K);
    cudaGetSymbolAddress((void**)&V,  g_V);
    cudaGetSymbolAddress((void**)&P,  g_P);
    cudaGetSymbolAddress((void**)&AO, g_AO);
    cudaGetSymbolAddress((void**)&F,  g_fetch);
    __nv_bfloat16 *hidH,*hidL,*WqH,*WqL,*WkH,*WkL,*WvH,*WvL;
    __nv_bfloat16 *QH,*QL,*KH,*KL,*VTH,*VTL,*PH,*PL;
    __half *WoH,*WoL,*AOH;
    cudaGetSymbolAddress((void**)&hidH, g_hidH); cudaGetSymbolAddress((void**)&hidL, g_hidL);
    cudaGetSymbolAddress((void**)&WqH,  g_WqH);  cudaGetSymbolAddress((void**)&WqL,  g_WqL);
    cudaGetSymbolAddress((void**)&WkH,  g_WkH);  cudaGetSymbolAddress((void**)&WkL,  g_WkL);
    cudaGetSymbolAddress((void**)&WvH,  g_WvH);  cudaGetSymbolAddress((void**)&WvL,  g_WvL);
    cudaGetSymbolAddress((void**)&QH,   g_QH);   cudaGetSymbolAddress((void**)&QL,   g_QL);
    cudaGetSymbolAddress((void**)&KH,   g_KH);   cudaGetSymbolAddress((void**)&KL,   g_KL);
    cudaGetSymbolAddress((void**)&VTH,  g_VTH);  cudaGetSymbolAddress((void**)&VTL,  g_VTL);
    cudaGetSymbolAddress((void**)&PH,   g_PH);   cudaGetSymbolAddress((void**)&PL,   g_PL);
    cudaGetSymbolAddress((void**)&WoH,  g_WoH);  cudaGetSymbolAddress((void**)&WoL,  g_WoL);
    cudaGetSymbolAddress((void**)&AOH,  g_AOH);

    const float scale = 0.08838834764831845f;
    dim3 blk(256);

    split_arr(hidden, hidH, hidL, (size_t)S_LEN * D_DIM);
    split_arr(Wq, WqH, WqL, (size_t)D_DIM * D_DIM);
    split_arr(Wk, WkH, WkL, (size_t)NKV * HD * D_DIM);
    split_arr(Wv, WvH, WvL, (size_t)NKV * HD * D_DIM);
    {
        int n4 = (int)((size_t)D_DIM * D_DIM / 4);
        split_h_hl<<<(n4 + 255) / 256, 256>>>((const float4*)Wo, (uint2*)WoH, (uint2*)WoL, n4);
    }

    // Projections
    bgemm3<0><<<dim3(D_DIM / BN, S_LEN / BM, 1), blk, SMEM4>>>(
        hidH, hidL, D_DIM, 0, WqH, WqL, D_DIM, 0, 1, Q, D_DIM, 0, D_DIM, 1.f, 0);
    bgemm3<0><<<dim3((NKV * HD) / BN, S_LEN / BM, 1), blk, SMEM4>>>(
        hidH, hidL, D_DIM, 0, WkH, WkL, D_DIM, 0, 1, K, NKV * HD, 0, D_DIM, 1.f, 0);
    bgemm3<0><<<dim3((NKV * HD) / BN, S_LEN / BM, 1), blk, SMEM4>>>(
        hidH, hidL, D_DIM, 0, WvH, WvL, D_DIM, 0, 1, V, NKV * HD, 0, D_DIM, 1.f, 0);

    rope_kernel<<<S_LEN, 256>>>(Q, NH,  cosb, sinb);
    rope_kernel<<<S_LEN, 256>>>(K, NKV, cosb, sinb);
    split_arr(Q, QH, QL, (size_t)S_LEN * D_DIM);
    split_arr(K, KH, KL, (size_t)S_LEN * NKV * HD);
    transpose_v<<<dim3(S_LEN / 32, HD / 32, NKV), dim3(32, 8)>>>(V, VTH, VTL);

    // Scores: causal lower-triangle blocks only
    bgemm3<1><<<dim3(36, 1, NH), blk, SMEM4>>>(
        QH, QL, D_DIM, HD, KH, KL, NKV * HD, HD, 4,
        P, S_LEN, (long long)S_LEN * S_LEN, HD, scale, 0);

    stats_kernel<<<S_LEN, 256>>>(P, F);
    softmax_select<<<dim3(S_LEN, NH), 256>>>(P, F, Q, K, PH, PL);

    // PV with causal K clamp
    bgemm3<0><<<dim3(HD / BN, S_LEN / BM, NH), blk, SMEM4>>>(
        PH, PL, S_LEN, (long long)S_LEN * S_LEN, VTH, VTL, S_LEN, (long long)HD * S_LEN, 4,
        AO, D_DIM, HD, S_LEN, 1.f, 1);

    {
        int n4 = (int)((size_t)S_LEN * D_DIM / 4);
        split_h_h<<<(n4 + 255) / 256, 256>>>((const float4*)AO, (uint2*)AOH, n4);
    }

    // Output projection: fp16 2-pass, cp.async
    hgemm2<<<dim3(D_DIM / BN, S_LEN / BM, 1), blk, SMEM3>>>(
        AOH, D_DIM, WoH, WoL, D_DIM, out, D_DIM, D_DIM);

    (void)in_sizes; (void)n_in; (void)out_size;
}